// round 3
// baseline (speedup 1.0000x reference)
#include <cuda_runtime.h>
#include <math.h>

#define NN 500000
#define EE 5000000
#define D 16
#define LRf 0.005f

#define NODE_BLOCKS ((NN + 255) / 256)
#define DEG_BLOCKS ((EE + 255) / 256)
#define EDGE_BLOCKS ((4 * EE + 255) / 256)
#define STR 20  // shared row stride (floats): conflict-free for float4 STS + LDS

// Scratch (static device globals; no allocation at runtime)
__device__ float g_deg[NN];
__device__ float g_dinv[NN];
__device__ float g_h[NN * D];
__device__ float g_A[NN * D];
__device__ float g_B[NN * D];
__device__ float g_dW[D * D];   // summed over layers, [in][out]
__device__ float g_db[D];       // summed over layers
__device__ double g_good[3];    // per-layer sum(z*z)

__device__ __forceinline__ float* buf_sel(int sel) {
    return (sel == 1) ? g_A : g_B;
}

// ---------------- init: deg=1 (self loop), zero accumulators ----------------
__global__ void k_init() {
    int i = blockIdx.x * blockDim.x + threadIdx.x;
    if (i < NN) g_deg[i] = 1.0f;
    if (i < D * D) g_dW[i] = 0.0f;
    if (i < D) g_db[i] = 0.0f;
    if (i < 3) g_good[i] = 0.0;
}

// ---------------- degree count over dst ----------------
__global__ void k_deg(const int* __restrict__ dst) {
    int e = blockIdx.x * blockDim.x + threadIdx.x;
    if (e < EE) atomicAdd(&g_deg[dst[e]], 1.0f);
}

__global__ void k_dinv() {
    int i = blockIdx.x * blockDim.x + threadIdx.x;
    if (i < NN) g_dinv[i] = rsqrtf(g_deg[i]);
}

// ---------------- h = x @ W^T ; out = dinv^2 * h (self-loop init) ----------------
__global__ void k_h(int xsel, const float* __restrict__ xin,
                    const float* __restrict__ W, int osel) {
    __shared__ float sW[D * D];
    int tid = threadIdx.x;
    sW[tid] = W[tid];  // blockDim == 256 == D*D
    __syncthreads();

    int n = blockIdx.x * 256 + tid;
    if (n >= NN) return;

    const float* x = (xsel == 0) ? xin : buf_sel(xsel);
    float* out = buf_sel(osel);

    float xv[D];
    const float4* xr = (const float4*)(x + (size_t)n * D);
#pragma unroll
    for (int q = 0; q < 4; q++) {
        float4 v = xr[q];
        xv[4 * q + 0] = v.x; xv[4 * q + 1] = v.y;
        xv[4 * q + 2] = v.z; xv[4 * q + 3] = v.w;
    }
    float dv = g_dinv[n];
    float sl = dv * dv;

    float4* hdst = (float4*)(g_h + (size_t)n * D);
    float4* odst = (float4*)(out + (size_t)n * D);
#pragma unroll
    for (int q = 0; q < 4; q++) {
        float hq[4];
#pragma unroll
        for (int r = 0; r < 4; r++) {
            int j = 4 * q + r;
            float s = 0.f;
#pragma unroll
            for (int k = 0; k < D; k++) s = fmaf(xv[k], sW[j * D + k], s);
            hq[r] = s;
        }
        float4 hv = make_float4(hq[0], hq[1], hq[2], hq[3]);
        hdst[q] = hv;
        odst[q] = make_float4(sl * hv.x, sl * hv.y, sl * hv.z, sl * hv.w);
    }
}

// ---------------- edge scatter: out[dst] += dinv[s]*dinv[d] * h[src] ----------------
__global__ void k_edge(const int* __restrict__ src, const int* __restrict__ dst,
                       int osel) {
    int t = blockIdx.x * blockDim.x + threadIdx.x;
    if (t >= 4 * EE) return;
    int e = t >> 2;
    int c = t & 3;
    int s = src[e];
    int d = dst[e];
    float norm = g_dinv[s] * g_dinv[d];
    float4 hv = ((const float4*)g_h)[(size_t)s * 4 + c];
    float4 v = make_float4(norm * hv.x, norm * hv.y, norm * hv.z, norm * hv.w);
    float* out = buf_sel(osel);
#if __CUDA_ARCH__ >= 900
    atomicAdd(((float4*)out) + (size_t)d * 4 + c, v);
#else
    float* p = out + (size_t)d * 16 + 4 * c;
    atomicAdd(p + 0, v.x); atomicAdd(p + 1, v.y);
    atomicAdd(p + 2, v.z); atomicAdd(p + 3, v.w);
#endif
}

// ---------------- epilogue: z = relu(out+b) (in place), goodness, dW, db ----------------
__global__ void k_epi(int xsel, const float* __restrict__ xin, int zsel,
                      const float* __restrict__ bvec, int layer) {
    __shared__ float sx[256 * STR];
    __shared__ float swd[256 * STR];
    __shared__ float sb[D];
    __shared__ float sred[8];

    int tid = threadIdx.x;
    if (tid < D) sb[tid] = bvec[tid];
    __syncthreads();

    const float* xprev = (xsel == 0) ? xin : buf_sel(xsel);
    float* zbuf = buf_sel(zsel);

    int n = blockIdx.x * 256 + tid;
    float gpart = 0.f;
    if (n < NN) {
        float4* zp = (float4*)(zbuf + (size_t)n * D);
        const float4* xp = (const float4*)(xprev + (size_t)n * D);
#pragma unroll
        for (int q = 0; q < 4; q++) {
            float4 o = zp[q];
            float4 xv = xp[q];
            float z0 = fmaxf(o.x + sb[4 * q + 0], 0.f);
            float z1 = fmaxf(o.y + sb[4 * q + 1], 0.f);
            float z2 = fmaxf(o.z + sb[4 * q + 2], 0.f);
            float z3 = fmaxf(o.w + sb[4 * q + 3], 0.f);
            zp[q] = make_float4(z0, z1, z2, z3);
            gpart += z0 * z0 + z1 * z1 + z2 * z2 + z3 * z3;
            ((float4*)(sx + tid * STR))[q] = xv;
            ((float4*)(swd + tid * STR))[q] =
                make_float4(4.f * z0 * z0, 4.f * z1 * z1,
                            4.f * z2 * z2, 4.f * z3 * z3);
        }
    } else {
#pragma unroll
        for (int q = 0; q < 4; q++) {
            ((float4*)(sx + tid * STR))[q] = make_float4(0.f, 0.f, 0.f, 0.f);
            ((float4*)(swd + tid * STR))[q] = make_float4(0.f, 0.f, 0.f, 0.f);
        }
    }
    __syncthreads();

    // dW[a][b] partial: thread (a,b) reduces over the block's 256 nodes.
    int a = tid & 15;
    int b = tid >> 4;
    float accW = 0.f, accB = 0.f;
#pragma unroll 8
    for (int i = 0; i < 256; i++) {
        float w = swd[i * STR + b];
        accW = fmaf(sx[i * STR + a], w, accW);
        accB += w;
    }
    atomicAdd(&g_dW[a * D + b], accW);
    if (a == 0) atomicAdd(&g_db[b], accB);

    // goodness block reduce -> double accumulator
#pragma unroll
    for (int off = 16; off > 0; off >>= 1)
        gpart += __shfl_xor_sync(0xffffffffu, gpart, off);
    if ((tid & 31) == 0) sred[tid >> 5] = gpart;
    __syncthreads();
    if (tid == 0) {
        float s = 0.f;
#pragma unroll
        for (int w2 = 0; w2 < 8; w2++) s += sred[w2];
        atomicAdd(&g_good[layer], (double)s);
    }
}

// ---------------- final: loss + weight update output ----------------
__device__ __forceinline__ float local_loss_dev(float g, int positive) {
    if (positive) {
        if (g > 10.f) return 0.f;
        if (g < -10.f) return -g;
        return log1pf(expf(-g));
    } else {
        if (g > 10.f) return g;
        if (g < -10.f) return 0.f;
        return log1pf(expf(g));
    }
}

__global__ void k_final(const float* __restrict__ W1, const float* __restrict__ b1,
                        const int* __restrict__ positive, float* __restrict__ out) {
    int tid = threadIdx.x;
    if (tid == 0) {
        int p = positive[0];
        float agg = 0.f;
        for (int l = 0; l < 3; l++) {
            float g = (float)g_good[l] * (1.0f / D);
            agg += local_loss_dev(g, p);
        }
        out[0] = agg;
    }
    if (tid >= 1 && tid < 257) {
        int o = (tid - 1) >> 4;
        int i = (tid - 1) & 15;
        // Wc[o][i] = W1[o][i] - LR * dW[i][o]
        out[tid] = W1[o * D + i] - LRf * g_dW[i * D + o];
    }
    if (tid >= 257 && tid < 273) {
        int j = tid - 257;
        out[tid] = b1[j] - LRf * g_db[j];
    }
}

extern "C" void kernel_launch(void* const* d_in, const int* in_sizes, int n_in,
                              void* d_out, int out_size) {
    const float* x = (const float*)d_in[0];
    const int* ei = (const int*)d_in[1];
    const float* W1 = (const float*)d_in[2];
    const float* b1 = (const float*)d_in[3];
    const float* W2 = (const float*)d_in[4];
    const float* b2 = (const float*)d_in[5];
    const float* W3 = (const float*)d_in[6];
    const float* b3 = (const float*)d_in[7];
    const int* positive = (const int*)d_in[8];
    float* out = (float*)d_out;

    const int* src = ei;        // edge_index[0]
    const int* dst = ei + EE;   // edge_index[1]

    k_init<<<NODE_BLOCKS, 256>>>();
    k_deg<<<DEG_BLOCKS, 256>>>(dst);
    k_dinv<<<NODE_BLOCKS, 256>>>();

    const float* Ws[3] = {W1, W2, W3};
    const float* bs[3] = {b1, b2, b3};
    // layer l: x from xsel, aggregate into osel (ping-pong A/B)
    int xsels[3] = {0, 1, 2};
    int osels[3] = {1, 2, 1};

    for (int l = 0; l < 3; l++) {
        k_h<<<NODE_BLOCKS, 256>>>(xsels[l], x, Ws[l], osels[l]);
        k_edge<<<EDGE_BLOCKS, 256>>>(src, dst, osels[l]);
        k_epi<<<NODE_BLOCKS, 256>>>(xsels[l], x, osels[l], bs[l], l);
    }

    k_final<<<1, 288>>>(W1, b1, positive, out);
}

// round 4
// speedup vs baseline: 1.1976x; 1.1976x over previous
#include <cuda_runtime.h>
#include <math.h>

#define NN 500000
#define EE 5000000
#define D 16
#define LRf 0.005f

#define NODE_BLOCKS ((NN + 255) / 256)   // 1954
#define EDGE_BLOCKS256 ((EE + 255) / 256)
#define GATHER_BLOCKS ((NN + 63) / 64)
#define NBLK NODE_BLOCKS
#define STR 20  // shared row stride (floats): conflict-free float4 STS/LDS

// ---------------- scratch (static device globals) ----------------
__device__ int   g_cnt[NN];        // in-degree (excl. self loop)
__device__ int   g_roff[NN];       // CSR row start
__device__ int   g_fill[NN];       // scatter cursors
__device__ int   g_bsum[NBLK];     // per-block count sums
__device__ int   g_boff[NBLK];     // exclusive block offsets
__device__ float g_dinv[NN];
__device__ float2 g_epay[EE];      // sorted-by-dst payload: {src(as float bits), norm}
__device__ float g_h[NN * D];
__device__ float g_A[NN * D];
__device__ float g_B[NN * D];
__device__ float g_dW[D * D];      // [in][out], summed over layers
__device__ float g_db[D];
__device__ double g_good[3];

__device__ __forceinline__ float* buf_sel(int sel) {
    return (sel == 1) ? g_A : g_B;
}

// ---------------- init ----------------
__global__ void k_init() {
    int i = blockIdx.x * blockDim.x + threadIdx.x;
    if (i < NN) g_cnt[i] = 0;
    if (i < D * D) g_dW[i] = 0.0f;
    if (i < D) g_db[i] = 0.0f;
    if (i < 3) g_good[i] = 0.0;
}

// ---------------- degree (int) ----------------
__global__ void k_cnt(const int* __restrict__ dst) {
    int e = blockIdx.x * blockDim.x + threadIdx.x;
    if (e < EE) atomicAdd(&g_cnt[dst[e]], 1);
}

__global__ void k_dinv() {
    int i = blockIdx.x * blockDim.x + threadIdx.x;
    if (i < NN) g_dinv[i] = rsqrtf((float)(g_cnt[i] + 1));  // +1 self loop
}

// ---------------- scan stage 1: per-block sums ----------------
__global__ void k_scan1() {
    __shared__ int sh[256];
    int tid = threadIdx.x;
    int n = blockIdx.x * 256 + tid;
    sh[tid] = (n < NN) ? g_cnt[n] : 0;
    __syncthreads();
#pragma unroll
    for (int off = 128; off > 0; off >>= 1) {
        if (tid < off) sh[tid] += sh[tid + off];
        __syncthreads();
    }
    if (tid == 0) g_bsum[blockIdx.x] = sh[0];
}

// ---------------- scan stage 2: exclusive scan of 1954 block sums (1 block) ----------------
__global__ void k_scan2() {
    __shared__ int a[1024], b[1024];
    int t = threadIdx.x;  // 1024 threads
    int v0 = (2 * t < NBLK) ? g_bsum[2 * t] : 0;
    int v1 = (2 * t + 1 < NBLK) ? g_bsum[2 * t + 1] : 0;
    a[t] = v0 + v1;
    __syncthreads();
    int* cur = a; int* nxt = b;
#pragma unroll
    for (int off = 1; off < 1024; off <<= 1) {
        int val = cur[t];
        if (t >= off) val += cur[t - off];
        nxt[t] = val;
        __syncthreads();
        int* tmp = cur; cur = nxt; nxt = tmp;
    }
    int excl = (t > 0) ? cur[t - 1] : 0;  // exclusive prefix of pair t
    if (2 * t < NBLK) g_boff[2 * t] = excl;
    if (2 * t + 1 < NBLK) g_boff[2 * t + 1] = excl + v0;
}

// ---------------- scan stage 3: per-node offsets ----------------
__global__ void k_scan3() {
    __shared__ int a[256], b[256];
    int tid = threadIdx.x;
    int n = blockIdx.x * 256 + tid;
    int c = (n < NN) ? g_cnt[n] : 0;
    a[tid] = c;
    __syncthreads();
    int* cur = a; int* nxt = b;
#pragma unroll
    for (int off = 1; off < 256; off <<= 1) {
        int val = cur[tid];
        if (tid >= off) val += cur[tid - off];
        nxt[tid] = val;
        __syncthreads();
        int* tmp = cur; cur = nxt; nxt = tmp;
    }
    if (n < NN) {
        int excl = cur[tid] - c;  // inclusive - self = exclusive
        int start = g_boff[blockIdx.x] + excl;
        g_roff[n] = start;
        g_fill[n] = start;
    }
}

// ---------------- scatter edge payloads into dst-sorted order ----------------
__global__ void k_scatter(const int* __restrict__ src, const int* __restrict__ dst) {
    int e = blockIdx.x * blockDim.x + threadIdx.x;
    if (e >= EE) return;
    int s = src[e];
    int d = dst[e];
    float norm = g_dinv[s] * g_dinv[d];
    int pos = atomicAdd(&g_fill[d], 1);
    g_epay[pos] = make_float2(__int_as_float(s), norm);
}

// ---------------- h = x @ W^T ----------------
__global__ void k_h(int xsel, const float* __restrict__ xin,
                    const float* __restrict__ W) {
    __shared__ float sW[D * D];
    int tid = threadIdx.x;
    sW[tid] = W[tid];  // blockDim == 256 == D*D
    __syncthreads();

    int n = blockIdx.x * 256 + tid;
    if (n >= NN) return;
    const float* x = (xsel == 0) ? xin : buf_sel(xsel);

    float xv[D];
    const float4* xr = (const float4*)(x + (size_t)n * D);
#pragma unroll
    for (int q = 0; q < 4; q++) {
        float4 v = xr[q];
        xv[4 * q + 0] = v.x; xv[4 * q + 1] = v.y;
        xv[4 * q + 2] = v.z; xv[4 * q + 3] = v.w;
    }
    float4* hdst = (float4*)(g_h + (size_t)n * D);
#pragma unroll
    for (int q = 0; q < 4; q++) {
        float hq[4];
#pragma unroll
        for (int r = 0; r < 4; r++) {
            int j = 4 * q + r;
            float s = 0.f;
#pragma unroll
            for (int k = 0; k < D; k++) s = fmaf(xv[k], sW[j * D + k], s);
            hq[r] = s;
        }
        hdst[q] = make_float4(hq[0], hq[1], hq[2], hq[3]);
    }
}

// ---------------- CSR gather: out[n] = dinv[n]^2 h[n] + sum norm_e h[src_e] ----------------
// 4 threads per node; thread c handles columns 4c..4c+3.
__global__ void k_gather(int osel) {
    int tid = blockIdx.x * blockDim.x + threadIdx.x;
    int n = tid >> 2;
    int c = tid & 3;
    if (n >= NN) return;

    int start = g_roff[n];
    int cnt = g_cnt[n];
    float dv = g_dinv[n];
    const float4* h4 = (const float4*)g_h;
    float4 hv = h4[(size_t)n * 4 + c];
    float sl = dv * dv;
    float ax = sl * hv.x, ay = sl * hv.y, az = sl * hv.z, aw = sl * hv.w;

#pragma unroll 2
    for (int j = 0; j < cnt; j++) {
        float2 p = g_epay[start + j];
        int s = __float_as_int(p.x);
        float norm = p.y;
        float4 h2 = h4[(size_t)s * 4 + c];
        ax = fmaf(norm, h2.x, ax);
        ay = fmaf(norm, h2.y, ay);
        az = fmaf(norm, h2.z, az);
        aw = fmaf(norm, h2.w, aw);
    }
    float* out = buf_sel(osel);
    ((float4*)out)[(size_t)n * 4 + c] = make_float4(ax, ay, az, aw);
}

// ---------------- epilogue: z = relu(out+b) in place, goodness, dW, db ----------------
__global__ void k_epi(int xsel, const float* __restrict__ xin, int zsel,
                      const float* __restrict__ bvec, int layer) {
    __shared__ float sx[256 * STR];
    __shared__ float swd[256 * STR];
    __shared__ float sb[D];
    __shared__ float sred[8];

    int tid = threadIdx.x;
    if (tid < D) sb[tid] = bvec[tid];
    __syncthreads();

    const float* xprev = (xsel == 0) ? xin : buf_sel(xsel);
    float* zbuf = buf_sel(zsel);

    int n = blockIdx.x * 256 + tid;
    float gpart = 0.f;
    if (n < NN) {
        float4* zp = (float4*)(zbuf + (size_t)n * D);
        const float4* xp = (const float4*)(xprev + (size_t)n * D);
#pragma unroll
        for (int q = 0; q < 4; q++) {
            float4 o = zp[q];
            float4 xv = xp[q];
            float z0 = fmaxf(o.x + sb[4 * q + 0], 0.f);
            float z1 = fmaxf(o.y + sb[4 * q + 1], 0.f);
            float z2 = fmaxf(o.z + sb[4 * q + 2], 0.f);
            float z3 = fmaxf(o.w + sb[4 * q + 3], 0.f);
            zp[q] = make_float4(z0, z1, z2, z3);
            gpart += z0 * z0 + z1 * z1 + z2 * z2 + z3 * z3;
            ((float4*)(sx + tid * STR))[q] = xv;
            ((float4*)(swd + tid * STR))[q] =
                make_float4(4.f * z0 * z0, 4.f * z1 * z1,
                            4.f * z2 * z2, 4.f * z3 * z3);
        }
    } else {
#pragma unroll
        for (int q = 0; q < 4; q++) {
            ((float4*)(sx + tid * STR))[q] = make_float4(0.f, 0.f, 0.f, 0.f);
            ((float4*)(swd + tid * STR))[q] = make_float4(0.f, 0.f, 0.f, 0.f);
        }
    }
    __syncthreads();

    int a = tid & 15;
    int b = tid >> 4;
    float accW = 0.f, accB = 0.f;
#pragma unroll 8
    for (int i = 0; i < 256; i++) {
        float w = swd[i * STR + b];
        accW = fmaf(sx[i * STR + a], w, accW);
        accB += w;
    }
    atomicAdd(&g_dW[a * D + b], accW);
    if (a == 0) atomicAdd(&g_db[b], accB);

#pragma unroll
    for (int off = 16; off > 0; off >>= 1)
        gpart += __shfl_xor_sync(0xffffffffu, gpart, off);
    if ((tid & 31) == 0) sred[tid >> 5] = gpart;
    __syncthreads();
    if (tid == 0) {
        float s = 0.f;
#pragma unroll
        for (int w2 = 0; w2 < 8; w2++) s += sred[w2];
        atomicAdd(&g_good[layer], (double)s);
    }
}

// ---------------- final ----------------
__device__ __forceinline__ float local_loss_dev(float g, int positive) {
    if (positive) {
        if (g > 10.f) return 0.f;
        if (g < -10.f) return -g;
        return log1pf(expf(-g));
    } else {
        if (g > 10.f) return g;
        if (g < -10.f) return 0.f;
        return log1pf(expf(g));
    }
}

__global__ void k_final(const float* __restrict__ W1, const float* __restrict__ b1,
                        const int* __restrict__ positive, float* __restrict__ out) {
    int tid = threadIdx.x;
    if (tid == 0) {
        int p = positive[0];
        float agg = 0.f;
        for (int l = 0; l < 3; l++) {
            float g = (float)g_good[l] * (1.0f / D);
            agg += local_loss_dev(g, p);
        }
        out[0] = agg;
    }
    if (tid >= 1 && tid < 257) {
        int o = (tid - 1) >> 4;
        int i = (tid - 1) & 15;
        out[tid] = W1[o * D + i] - LRf * g_dW[i * D + o];
    }
    if (tid >= 257 && tid < 273) {
        int j = tid - 257;
        out[tid] = b1[j] - LRf * g_db[j];
    }
}

extern "C" void kernel_launch(void* const* d_in, const int* in_sizes, int n_in,
                              void* d_out, int out_size) {
    const float* x = (const float*)d_in[0];
    const int* ei = (const int*)d_in[1];
    const float* W1 = (const float*)d_in[2];
    const float* b1 = (const float*)d_in[3];
    const float* W2 = (const float*)d_in[4];
    const float* b2 = (const float*)d_in[5];
    const float* W3 = (const float*)d_in[6];
    const float* b3 = (const float*)d_in[7];
    const int* positive = (const int*)d_in[8];
    float* out = (float*)d_out;

    const int* src = ei;
    const int* dst = ei + EE;

    // ---- build CSR (once per launch) ----
    k_init<<<NODE_BLOCKS, 256>>>();
    k_cnt<<<EDGE_BLOCKS256, 256>>>(dst);
    k_dinv<<<NODE_BLOCKS, 256>>>();
    k_scan1<<<NODE_BLOCKS, 256>>>();
    k_scan2<<<1, 1024>>>();
    k_scan3<<<NODE_BLOCKS, 256>>>();
    k_scatter<<<EDGE_BLOCKS256, 256>>>(src, dst);

    const float* Ws[3] = {W1, W2, W3};
    const float* bs[3] = {b1, b2, b3};
    int xsels[3] = {0, 1, 2};
    int osels[3] = {1, 2, 1};

    for (int l = 0; l < 3; l++) {
        k_h<<<NODE_BLOCKS, 256>>>(xsels[l], x, Ws[l]);
        k_gather<<<GATHER_BLOCKS, 256>>>(osels[l]);
        k_epi<<<NODE_BLOCKS, 256>>>(xsels[l], x, osels[l], bs[l], l);
    }

    k_final<<<1, 288>>>(W1, b1, positive, out);
}